// round 3
// baseline (speedup 1.0000x reference)
#include <cuda_runtime.h>
#include <math.h>

#define N_NODES 25000
#define N_EDGES 400000
#define HID 64
#define HEADS 4
#define D1 (HID*HEADS)

// ---------------- scratch (static device globals; no allocation) -------------
__device__ float g_h[N_NODES * HID];
__device__ float g_x[N_NODES * D1];
__device__ int   g_deg[N_NODES];
__device__ int   g_off[N_NODES + 1];
__device__ int   g_cur[N_NODES];
__device__ int   g_csr[N_EDGES];

__device__ __forceinline__ float ex2_approx(float x) {
    float r;
    asm("ex2.approx.ftz.f32 %0, %1;" : "=f"(r) : "f"(x));
    return r;
}

__device__ __forceinline__ unsigned cvt_tf32(float f) {
    unsigned u;
    asm("cvt.rna.tf32.f32 %0, %1;" : "=r"(u) : "f"(f));
    return u;
}

__device__ __forceinline__ void mma_tf32(float* c,
    unsigned a0, unsigned a1, unsigned a2, unsigned a3,
    unsigned b0, unsigned b1) {
    asm("mma.sync.aligned.m16n8k8.row.col.f32.tf32.tf32.f32 "
        "{%0,%1,%2,%3},{%4,%5,%6,%7},{%8,%9},{%0,%1,%2,%3};"
        : "+f"(c[0]), "+f"(c[1]), "+f"(c[2]), "+f"(c[3])
        : "r"(a0), "r"(a1), "r"(a2), "r"(a3), "r"(b0), "r"(b1));
}

// ---------------- CSR build --------------------------------------------------
__global__ void k_zero(int* a, int n) {
    int i = blockIdx.x * blockDim.x + threadIdx.x;
    if (i < n) a[i] = 0;
}

__global__ void k_count(const int* __restrict__ recv, int* __restrict__ deg, int E) {
    int i = blockIdx.x * blockDim.x + threadIdx.x;
    if (i < E) atomicAdd(&deg[recv[i]], 1);
}

__global__ __launch_bounds__(1024)
void k_scan(const int* __restrict__ deg, int* __restrict__ off,
            int* __restrict__ cur, int n) {
    __shared__ int wsum[32];
    __shared__ int carry_s;
    int t    = threadIdx.x;
    int lane = t & 31;
    int wid  = t >> 5;
    if (t == 0) { carry_s = 0; off[0] = 0; }
    __syncthreads();
    for (int base = 0; base < n; base += 1024) {
        int i = base + t;
        int v = (i < n) ? deg[i] : 0;
        int s = v;
#pragma unroll
        for (int o = 1; o < 32; o <<= 1) {
            int u = __shfl_up_sync(0xffffffffu, s, o);
            if (lane >= o) s += u;
        }
        if (lane == 31) wsum[wid] = s;
        __syncthreads();
        if (wid == 0) {
            int ws = wsum[lane];
#pragma unroll
            for (int o = 1; o < 32; o <<= 1) {
                int u = __shfl_up_sync(0xffffffffu, ws, o);
                if (lane >= o) ws += u;
            }
            wsum[lane] = ws;
        }
        __syncthreads();
        int prev  = (wid > 0) ? wsum[wid - 1] : 0;
        int carry = carry_s;
        int incl  = carry + prev + s;
        if (i < n) {
            off[i + 1] = incl;
            cur[i]     = incl - v;
        }
        __syncthreads();
        if (t == 1023) carry_s = incl;
        __syncthreads();
    }
}

__global__ void k_scatter(const int* __restrict__ recv, const int* __restrict__ send,
                          int* __restrict__ cur, int* __restrict__ csr, int E) {
    int i = blockIdx.x * blockDim.x + threadIdx.x;
    if (i < E) {
        int r = recv[i];
        int p = atomicAdd(&cur[r], 1);
        csr[p] = send[i];
    }
}

// ---------------- 3xTF32 tensor-core GEMM ------------------------------------
// h[M,64] = x[M,K] @ Wq[K,64] + bq, fp32-accurate via hi/lo tf32 split.
// Block: 128 rows x 64 cols, 256 thr = 8 warps; warp = 16 rows x 64 cols.
// Kc=16 stage; hi/lo split done once at staging time.
#define KC 16

__global__ __launch_bounds__(256)
void k_gemm_tf32(const float* __restrict__ x, const float* __restrict__ Wq,
                 const float* __restrict__ bq, float* __restrict__ h,
                 int M, int K) {
    __shared__ float Ah[128][20];   // stride 20: frag loads bank-bijective
    __shared__ float Al[128][20];
    __shared__ float4 Bf[2 * 8 * 32];  // [ck][ntile][lane] -> (b0h,b1h,b0l,b1l)

    int t    = threadIdx.x;
    int lane = t & 31;
    int wid  = t >> 5;
    int gid  = lane >> 2;
    int tig  = lane & 3;
    int m0   = blockIdx.x * 128;

    float acc[8][4];
#pragma unroll
    for (int nt = 0; nt < 8; nt++)
#pragma unroll
        for (int q = 0; q < 4; q++) acc[nt][q] = 0.f;

    for (int k0 = 0; k0 < K; k0 += KC) {
        // ---- stage A (128 x 16), hi/lo split ----
#pragma unroll
        for (int i = 0; i < 2; i++) {
            int f = t + i * 256;          // float4 index, 512 total
            int r = f >> 2;
            int c = (f & 3) * 4;
            int gr = m0 + r;
            float4 v = (gr < M) ? *(const float4*)&x[gr * K + k0 + c]
                                : make_float4(0.f, 0.f, 0.f, 0.f);
            float4 vh, vl;
            vh.x = __uint_as_float(cvt_tf32(v.x)); vl.x = __uint_as_float(cvt_tf32(v.x - vh.x));
            vh.y = __uint_as_float(cvt_tf32(v.y)); vl.y = __uint_as_float(cvt_tf32(v.y - vh.y));
            vh.z = __uint_as_float(cvt_tf32(v.z)); vl.z = __uint_as_float(cvt_tf32(v.z - vh.z));
            vh.w = __uint_as_float(cvt_tf32(v.w)); vl.w = __uint_as_float(cvt_tf32(v.w - vh.w));
            *(float4*)&Ah[r][c] = vh;
            *(float4*)&Al[r][c] = vl;
        }
        // ---- stage B (16 x 64) into fragment order ----
        {
            int k  = t >> 4;              // 0..15
            int n4 = (t & 15) * 4;        // 0..60
            float4 wv = *(const float4*)&Wq[(k0 + k) * 64 + n4];
            int ck   = k >> 3;
            int kl   = k & 7;
            int reg  = kl >> 2;
            int tig2 = kl & 3;
            float vv[4] = {wv.x, wv.y, wv.z, wv.w};
#pragma unroll
            for (int j = 0; j < 4; j++) {
                int n = n4 + j;
                int nt = n >> 3, gid2 = n & 7;
                float* slot = (float*)&Bf[(ck * 8 + nt) * 32 + gid2 * 4 + tig2];
                float fh = __uint_as_float(cvt_tf32(vv[j]));
                float fl = __uint_as_float(cvt_tf32(vv[j] - fh));
                slot[reg]     = fh;
                slot[2 + reg] = fl;
            }
        }
        __syncthreads();
        // ---- compute 2 k-chunks ----
#pragma unroll
        for (int ck = 0; ck < 2; ck++) {
            int kb = ck * 8;
            int row = wid * 16 + gid;
            unsigned ah0 = __float_as_uint(Ah[row][kb + tig]);
            unsigned ah1 = __float_as_uint(Ah[row + 8][kb + tig]);
            unsigned ah2 = __float_as_uint(Ah[row][kb + tig + 4]);
            unsigned ah3 = __float_as_uint(Ah[row + 8][kb + tig + 4]);
            unsigned al0 = __float_as_uint(Al[row][kb + tig]);
            unsigned al1 = __float_as_uint(Al[row + 8][kb + tig]);
            unsigned al2 = __float_as_uint(Al[row][kb + tig + 4]);
            unsigned al3 = __float_as_uint(Al[row + 8][kb + tig + 4]);
#pragma unroll
            for (int nt = 0; nt < 8; nt++) {
                float4 bb = Bf[(ck * 8 + nt) * 32 + lane];
                unsigned b0h = __float_as_uint(bb.x), b1h = __float_as_uint(bb.y);
                unsigned b0l = __float_as_uint(bb.z), b1l = __float_as_uint(bb.w);
                mma_tf32(acc[nt], ah0, ah1, ah2, ah3, b0h, b1h);
                mma_tf32(acc[nt], ah0, ah1, ah2, ah3, b0l, b1l);
                mma_tf32(acc[nt], al0, al1, al2, al3, b0h, b1h);
            }
        }
        __syncthreads();
    }

    // ---- epilogue: bias + store ----
    int r0 = m0 + wid * 16 + gid;
#pragma unroll
    for (int nt = 0; nt < 8; nt++) {
        int col = nt * 8 + 2 * tig;
        float2 bia = *(const float2*)&bq[col];
        if (r0 < M) {
            float2 o = make_float2(acc[nt][0] + bia.x, acc[nt][1] + bia.y);
            *(float2*)&h[r0 * HID + col] = o;
        }
        if (r0 + 8 < M) {
            float2 o = make_float2(acc[nt][2] + bia.x, acc[nt][3] + bia.y);
            *(float2*)&h[(r0 + 8) * HID + col] = o;
        }
    }
}

// ---------------- fused edge attention + aggregate ---------------------------
__global__ __launch_bounds__(256)
void k_edge(const float* __restrict__ h, const int* __restrict__ off,
            const int* __restrict__ csr, const float* __restrict__ Wl,
            const float* __restrict__ bl, float* __restrict__ out,
            int n, int last) {
    int w = (blockIdx.x * blockDim.x + threadIdx.x) >> 5;
    if (w >= n) return;
    int lane = threadIdx.x & 31;
    const float2* hv = (const float2*)h;

    float2 rv = hv[w * 32 + lane];

    const float L2E = 1.4426950408889634f;
    float W0[4], c0[4], c1[4];
#pragma unroll
    for (int a = 0; a < 4; a++) {
        float w0 = Wl[a];
        float w1 = Wl[4 + a];
        float b  = bl[a];
        W0[a] = w0 * L2E;
        c0[a] = fmaf(w1, rv.x, b) * L2E;
        c1[a] = fmaf(w1, rv.y, b) * L2E;
    }

    int beg = off[w], end = off[w + 1];
    bool has = end > beg;

    float den0[4] = {0.f, 0.f, 0.f, 0.f}, num0[4] = {0.f, 0.f, 0.f, 0.f};
    float den1[4] = {0.f, 0.f, 0.f, 0.f}, num1[4] = {0.f, 0.f, 0.f, 0.f};

    int i = beg;
    for (; i + 2 <= end; i += 2) {
        int sa = __ldg(&csr[i]);
        int sb = __ldg(&csr[i + 1]);
        float2 va = hv[sa * 32 + lane];
        float2 vb = hv[sb * 32 + lane];
#pragma unroll
        for (int a = 0; a < 4; a++) {
            float z, l, p;
            z = fmaf(W0[a], va.x, c0[a]); l = fmaxf(z, 0.2f * z); p = ex2_approx(l);
            den0[a] += p; num0[a] = fmaf(va.x, p, num0[a]);
            z = fmaf(W0[a], va.y, c1[a]); l = fmaxf(z, 0.2f * z); p = ex2_approx(l);
            den1[a] += p; num1[a] = fmaf(va.y, p, num1[a]);
            z = fmaf(W0[a], vb.x, c0[a]); l = fmaxf(z, 0.2f * z); p = ex2_approx(l);
            den0[a] += p; num0[a] = fmaf(vb.x, p, num0[a]);
            z = fmaf(W0[a], vb.y, c1[a]); l = fmaxf(z, 0.2f * z); p = ex2_approx(l);
            den1[a] += p; num1[a] = fmaf(vb.y, p, num1[a]);
        }
    }
    if (i < end) {
        int sa = __ldg(&csr[i]);
        float2 va = hv[sa * 32 + lane];
#pragma unroll
        for (int a = 0; a < 4; a++) {
            float z, l, p;
            z = fmaf(W0[a], va.x, c0[a]); l = fmaxf(z, 0.2f * z); p = ex2_approx(l);
            den0[a] += p; num0[a] = fmaf(va.x, p, num0[a]);
            z = fmaf(W0[a], va.y, c1[a]); l = fmaxf(z, 0.2f * z); p = ex2_approx(l);
            den1[a] += p; num1[a] = fmaf(va.y, p, num1[a]);
        }
    }

    if (last) {
        float acc0 = 0.f, acc1 = 0.f;
#pragma unroll
        for (int a = 0; a < 4; a++) {
            acc0 += has ? __fdividef(num0[a], den0[a]) : 0.f;
            acc1 += has ? __fdividef(num1[a], den1[a]) : 0.f;
        }
        float v0 = 0.25f * acc0;
        float v1 = 0.25f * acc1;
        v0 = (v0 > 0.f) ? v0 : expm1f(v0);
        v1 = (v1 > 0.f) ? v1 : expm1f(v1);
        *(float2*)&out[w * HID + 2 * lane] = make_float2(v0, v1);
    } else {
        float o[8];
#pragma unroll
        for (int a = 0; a < 4; a++) {
            float g = has ? __fdividef(num0[a], den0[a]) : 0.f;
            o[a] = (g > 0.f) ? g : expm1f(g);
        }
#pragma unroll
        for (int a = 0; a < 4; a++) {
            float g = has ? __fdividef(num1[a], den1[a]) : 0.f;
            o[4 + a] = (g > 0.f) ? g : expm1f(g);
        }
        *(float4*)&out[w * D1 + 8 * lane]     = make_float4(o[0], o[1], o[2], o[3]);
        *(float4*)&out[w * D1 + 8 * lane + 4] = make_float4(o[4], o[5], o[6], o[7]);
    }
}

// ---------------- launch ------------------------------------------------------
extern "C" void kernel_launch(void* const* d_in, const int* in_sizes, int n_in,
                              void* d_out, int out_size) {
    const float* nodes = (const float*)d_in[0];
    const int*   send  = (const int*)d_in[1];
    const int*   recv  = (const int*)d_in[2];
    const float* Wq0 = (const float*)d_in[3];
    const float* bq0 = (const float*)d_in[4];
    const float* Wl0 = (const float*)d_in[5];
    const float* bl0 = (const float*)d_in[6];
    const float* Wq1 = (const float*)d_in[7];
    const float* bq1 = (const float*)d_in[8];
    const float* Wl1 = (const float*)d_in[9];
    const float* bl1 = (const float*)d_in[10];
    const float* Wq2 = (const float*)d_in[11];
    const float* bq2 = (const float*)d_in[12];
    const float* Wl2 = (const float*)d_in[13];
    const float* bl2 = (const float*)d_in[14];
    float* out = (float*)d_out;

    float *h, *x;
    int *deg, *off, *cur, *csr;
    cudaGetSymbolAddress((void**)&h,   g_h);
    cudaGetSymbolAddress((void**)&x,   g_x);
    cudaGetSymbolAddress((void**)&deg, g_deg);
    cudaGetSymbolAddress((void**)&off, g_off);
    cudaGetSymbolAddress((void**)&cur, g_cur);
    cudaGetSymbolAddress((void**)&csr, g_csr);

    k_zero<<<(N_NODES + 255) / 256, 256>>>(deg, N_NODES);
    k_count<<<(N_EDGES + 255) / 256, 256>>>(recv, deg, N_EDGES);
    k_scan<<<1, 1024>>>(deg, off, cur, N_NODES);
    k_scatter<<<(N_EDGES + 255) / 256, 256>>>(recv, send, cur, csr, N_EDGES);

    int gemm_blocks = (N_NODES + 127) / 128;
    int edge_blocks = (N_NODES * 32 + 255) / 256;

    k_gemm_tf32<<<gemm_blocks, 256>>>(nodes, Wq0, bq0, h, N_NODES, 128);
    k_edge<<<edge_blocks, 256>>>(h, off, csr, Wl0, bl0, x, N_NODES, 0);
    k_gemm_tf32<<<gemm_blocks, 256>>>(x, Wq1, bq1, h, N_NODES, D1);
    k_edge<<<edge_blocks, 256>>>(h, off, csr, Wl1, bl1, x, N_NODES, 0);
    k_gemm_tf32<<<gemm_blocks, 256>>>(x, Wq2, bq2, h, N_NODES, D1);
    k_edge<<<edge_blocks, 256>>>(h, off, csr, Wl2, bl2, out, N_NODES, 1);
}

// round 4
// speedup vs baseline: 1.2364x; 1.2364x over previous
#include <cuda_runtime.h>
#include <math.h>

#define N_NODES 25000
#define N_EDGES 400000
#define HID 64
#define HEADS 4
#define D1 (HID*HEADS)

typedef unsigned long long u64;

// ---------------- scratch (static device globals; no allocation) -------------
__device__ float g_h[N_NODES * HID];
__device__ float g_x[N_NODES * D1];
__device__ int   g_deg[N_NODES];
__device__ int   g_off[N_NODES + 1];
__device__ int   g_cur[N_NODES];
__device__ int   g_csr[N_EDGES];

// ---------------- helpers -----------------------------------------------------
__device__ __forceinline__ float ex2_approx(float x) {
    float r;
    asm("ex2.approx.ftz.f32 %0, %1;" : "=f"(r) : "f"(x));
    return r;
}
__device__ __forceinline__ u64 pk2(float lo, float hi) {
    u64 r; asm("mov.b64 %0, {%1, %2};" : "=l"(r) : "f"(lo), "f"(hi)); return r;
}
__device__ __forceinline__ void upk2(float& lo, float& hi, u64 v) {
    asm("mov.b64 {%0, %1}, %2;" : "=f"(lo), "=f"(hi) : "l"(v));
}
__device__ __forceinline__ u64 fma2(u64 a, u64 b, u64 c) {
    u64 r; asm("fma.rn.f32x2 %0, %1, %2, %3;" : "=l"(r) : "l"(a), "l"(b), "l"(c)); return r;
}
__device__ __forceinline__ u64 mul2(u64 a, u64 b) {
    u64 r; asm("mul.rn.f32x2 %0, %1, %2;" : "=l"(r) : "l"(a), "l"(b)); return r;
}
__device__ __forceinline__ u64 add2(u64 a, u64 b) {
    u64 r; asm("add.rn.f32x2 %0, %1, %2;" : "=l"(r) : "l"(a), "l"(b)); return r;
}

// ---------------- CSR build --------------------------------------------------
__global__ void k_count(const int* __restrict__ recv, int* __restrict__ deg, int E) {
    int i = blockIdx.x * blockDim.x + threadIdx.x;
    if (i < E) atomicAdd(&deg[recv[i]], 1);
}

__global__ __launch_bounds__(1024)
void k_scan(const int* __restrict__ deg, int* __restrict__ off,
            int* __restrict__ cur, int n) {
    __shared__ int wsum[32];
    __shared__ int carry_s;
    int t    = threadIdx.x;
    int lane = t & 31;
    int wid  = t >> 5;
    if (t == 0) { carry_s = 0; off[0] = 0; }
    __syncthreads();
    for (int base = 0; base < n; base += 1024) {
        int i = base + t;
        int v = (i < n) ? deg[i] : 0;
        int s = v;
#pragma unroll
        for (int o = 1; o < 32; o <<= 1) {
            int u = __shfl_up_sync(0xffffffffu, s, o);
            if (lane >= o) s += u;
        }
        if (lane == 31) wsum[wid] = s;
        __syncthreads();
        if (wid == 0) {
            int ws = wsum[lane];
#pragma unroll
            for (int o = 1; o < 32; o <<= 1) {
                int u = __shfl_up_sync(0xffffffffu, ws, o);
                if (lane >= o) ws += u;
            }
            wsum[lane] = ws;
        }
        __syncthreads();
        int prev  = (wid > 0) ? wsum[wid - 1] : 0;
        int carry = carry_s;
        int incl  = carry + prev + s;
        if (i < n) {
            off[i + 1] = incl;
            cur[i]     = incl - v;
        }
        __syncthreads();
        if (t == 1023) carry_s = incl;
        __syncthreads();
    }
}

// scatter also re-zeroes deg (dead after k_scan) so the next replay starts clean.
__global__ void k_scatter(const int* __restrict__ recv, const int* __restrict__ send,
                          int* __restrict__ cur, int* __restrict__ csr,
                          int* __restrict__ deg, int E) {
    int i = blockIdx.x * blockDim.x + threadIdx.x;
    if (i < N_NODES) deg[i] = 0;
    if (i < E) {
        int r = recv[i];
        int p = atomicAdd(&cur[r], 1);
        csr[p] = send[i];
    }
}

// ---------------- SIMT GEMM: h[M,64] = x[M,K] @ Wq[K,64] + bq ----------------
#define GM_TM 128
#define GM_KC 32

__global__ __launch_bounds__(256)
void k_gemm(const float* __restrict__ x, const float* __restrict__ Wq,
            const float* __restrict__ bq, float* __restrict__ h,
            int M, int K) {
    __shared__ float As[GM_TM][GM_KC + 1];
    __shared__ float Bs[GM_KC][HID];
    int t  = threadIdx.x;
    int tx = t & 15;
    int ty = t >> 4;
    int m0 = blockIdx.x * GM_TM;

    float acc[8][4];
#pragma unroll
    for (int r = 0; r < 8; r++)
#pragma unroll
        for (int c = 0; c < 4; c++) acc[r][c] = 0.f;

    for (int k0 = 0; k0 < K; k0 += GM_KC) {
#pragma unroll
        for (int i = 0; i < 16; i++) {
            int e  = t + i * 256;
            int r  = e >> 5;
            int kk = e & 31;
            int gr = m0 + r;
            As[r][kk] = (gr < M) ? x[gr * K + k0 + kk] : 0.f;
        }
#pragma unroll
        for (int i = 0; i < 8; i++) {
            int e  = t + i * 256;
            int kk = e >> 6;
            int c  = e & 63;
            Bs[kk][c] = Wq[(k0 + kk) * HID + c];
        }
        __syncthreads();
#pragma unroll
        for (int kk = 0; kk < GM_KC; kk++) {
            float4 bv = *(const float4*)&Bs[kk][tx * 4];
#pragma unroll
            for (int r = 0; r < 8; r++) {
                float a = As[ty * 8 + r][kk];
                acc[r][0] = fmaf(a, bv.x, acc[r][0]);
                acc[r][1] = fmaf(a, bv.y, acc[r][1]);
                acc[r][2] = fmaf(a, bv.z, acc[r][2]);
                acc[r][3] = fmaf(a, bv.w, acc[r][3]);
            }
        }
        __syncthreads();
    }
    float4 bias = *(const float4*)&bq[tx * 4];
#pragma unroll
    for (int r = 0; r < 8; r++) {
        int gr = m0 + ty * 8 + r;
        if (gr < M) {
            float4 o;
            o.x = acc[r][0] + bias.x;
            o.y = acc[r][1] + bias.y;
            o.z = acc[r][2] + bias.z;
            o.w = acc[r][3] + bias.w;
            *(float4*)&h[gr * HID + tx * 4] = o;
        }
    }
}

// ---------------- fused edge attention + aggregate (f32x2 packed) ------------
// One warp per receiver node; lane owns hidden dims (2*lane, 2*lane+1), packed
// as one f32x2 register pair throughout. Logit coeffs pre-scaled by log2(e);
// leaky-relu applied in the exp2 domain (positive scaling commutes with max).
__global__ __launch_bounds__(256)
void k_edge(const float* __restrict__ h, const int* __restrict__ off,
            const int* __restrict__ csr, const float* __restrict__ Wl,
            const float* __restrict__ bl, float* __restrict__ out,
            int n, int last) {
    int w = (blockIdx.x * blockDim.x + threadIdx.x) >> 5;
    if (w >= n) return;
    int lane = threadIdx.x & 31;
    const u64* hv = (const u64*)h;

    float rvx, rvy;
    upk2(rvx, rvy, hv[w * 32 + lane]);

    const float L2E = 1.4426950408889634f;
    const u64 P02 = pk2(0.2f, 0.2f);
    u64 W0p[4], cp[4];
#pragma unroll
    for (int a = 0; a < 4; a++) {
        float w0 = Wl[a] * L2E;
        float w1 = Wl[4 + a];
        float b  = bl[a];
        W0p[a] = pk2(w0, w0);
        cp[a]  = pk2(fmaf(w1, rvx, b) * L2E, fmaf(w1, rvy, b) * L2E);
    }

    int beg = off[w], end = off[w + 1];
    bool has = end > beg;

    u64 den[4], num[4];
#pragma unroll
    for (int a = 0; a < 4; a++) { den[a] = pk2(0.f, 0.f); num[a] = pk2(0.f, 0.f); }

    int i = beg;
    for (; i + 2 <= end; i += 2) {
        int sa = __ldg(&csr[i]);
        int sb = __ldg(&csr[i + 1]);
        u64 pva = hv[sa * 32 + lane];
        u64 pvb = hv[sb * 32 + lane];
#pragma unroll
        for (int a = 0; a < 4; a++) {
            u64 z2 = fma2(W0p[a], pva, cp[a]);
            u64 zs = mul2(z2, P02);
            float zl, zh, sl, sh;
            upk2(zl, zh, z2); upk2(sl, sh, zs);
            float p0 = ex2_approx(fmaxf(zl, sl));
            float p1 = ex2_approx(fmaxf(zh, sh));
            u64 pp = pk2(p0, p1);
            den[a] = add2(den[a], pp);
            num[a] = fma2(pva, pp, num[a]);
        }
#pragma unroll
        for (int a = 0; a < 4; a++) {
            u64 z2 = fma2(W0p[a], pvb, cp[a]);
            u64 zs = mul2(z2, P02);
            float zl, zh, sl, sh;
            upk2(zl, zh, z2); upk2(sl, sh, zs);
            float p0 = ex2_approx(fmaxf(zl, sl));
            float p1 = ex2_approx(fmaxf(zh, sh));
            u64 pp = pk2(p0, p1);
            den[a] = add2(den[a], pp);
            num[a] = fma2(pvb, pp, num[a]);
        }
    }
    if (i < end) {
        int sa = __ldg(&csr[i]);
        u64 pva = hv[sa * 32 + lane];
#pragma unroll
        for (int a = 0; a < 4; a++) {
            u64 z2 = fma2(W0p[a], pva, cp[a]);
            u64 zs = mul2(z2, P02);
            float zl, zh, sl, sh;
            upk2(zl, zh, z2); upk2(sl, sh, zs);
            float p0 = ex2_approx(fmaxf(zl, sl));
            float p1 = ex2_approx(fmaxf(zh, sh));
            u64 pp = pk2(p0, p1);
            den[a] = add2(den[a], pp);
            num[a] = fma2(pva, pp, num[a]);
        }
    }

    // ---- finalize ----
    if (last) {
        float acc0 = 0.f, acc1 = 0.f;
#pragma unroll
        for (int a = 0; a < 4; a++) {
            float n0, n1, d0, d1;
            upk2(n0, n1, num[a]); upk2(d0, d1, den[a]);
            acc0 += has ? __fdividef(n0, d0) : 0.f;
            acc1 += has ? __fdividef(n1, d1) : 0.f;
        }
        float v0 = 0.25f * acc0;
        float v1 = 0.25f * acc1;
        v0 = (v0 > 0.f) ? v0 : expm1f(v0);
        v1 = (v1 > 0.f) ? v1 : expm1f(v1);
        *(float2*)&out[w * HID + 2 * lane] = make_float2(v0, v1);
    } else {
        float o[8];
#pragma unroll
        for (int a = 0; a < 4; a++) {
            float n0, n1, d0, d1;
            upk2(n0, n1, num[a]); upk2(d0, d1, den[a]);
            float g0 = has ? __fdividef(n0, d0) : 0.f;
            float g1 = has ? __fdividef(n1, d1) : 0.f;
            o[a]     = (g0 > 0.f) ? g0 : expm1f(g0);
            o[4 + a] = (g1 > 0.f) ? g1 : expm1f(g1);
        }
        *(float4*)&out[w * D1 + 8 * lane]     = make_float4(o[0], o[1], o[2], o[3]);
        *(float4*)&out[w * D1 + 8 * lane + 4] = make_float4(o[4], o[5], o[6], o[7]);
    }
}

// ---------------- launch ------------------------------------------------------
extern "C" void kernel_launch(void* const* d_in, const int* in_sizes, int n_in,
                              void* d_out, int out_size) {
    const float* nodes = (const float*)d_in[0];
    const int*   send  = (const int*)d_in[1];
    const int*   recv  = (const int*)d_in[2];
    const float* Wq0 = (const float*)d_in[3];
    const float* bq0 = (const float*)d_in[4];
    const float* Wl0 = (const float*)d_in[5];
    const float* bl0 = (const float*)d_in[6];
    const float* Wq1 = (const float*)d_in[7];
    const float* bq1 = (const float*)d_in[8];
    const float* Wl1 = (const float*)d_in[9];
    const float* bl1 = (const float*)d_in[10];
    const float* Wq2 = (const float*)d_in[11];
    const float* bq2 = (const float*)d_in[12];
    const float* Wl2 = (const float*)d_in[13];
    const float* bl2 = (const float*)d_in[14];
    float* out = (float*)d_out;

    float *h, *x;
    int *deg, *off, *cur, *csr;
    cudaGetSymbolAddress((void**)&h,   g_h);
    cudaGetSymbolAddress((void**)&x,   g_x);
    cudaGetSymbolAddress((void**)&deg, g_deg);
    cudaGetSymbolAddress((void**)&off, g_off);
    cudaGetSymbolAddress((void**)&cur, g_cur);
    cudaGetSymbolAddress((void**)&csr, g_csr);

    int gemm_blocks = (N_NODES + GM_TM - 1) / GM_TM;
    int edge_blocks = (N_NODES * 32 + 255) / 256;

    // launch index 3 (k_gemm) is the one ncu profiles — keep it there.
    k_count<<<(N_EDGES + 255) / 256, 256>>>(recv, deg, N_EDGES);          // 0
    k_scan<<<1, 1024>>>(deg, off, cur, N_NODES);                          // 1
    k_scatter<<<(N_EDGES + 255) / 256, 256>>>(recv, send, cur, csr, deg, N_EDGES); // 2
    k_gemm<<<gemm_blocks, 256>>>(nodes, Wq0, bq0, h, N_NODES, 128);       // 3 (profiled)
    k_edge<<<edge_blocks, 256>>>(h, off, csr, Wl0, bl0, x, N_NODES, 0);   // 4
    k_gemm<<<gemm_blocks, 256>>>(x, Wq1, bq1, h, N_NODES, D1);            // 5
    k_edge<<<edge_blocks, 256>>>(h, off, csr, Wl1, bl1, x, N_NODES, 0);   // 6
    k_gemm<<<gemm_blocks, 256>>>(x, Wq2, bq2, h, N_NODES, D1);            // 7
    k_edge<<<edge_blocks, 256>>>(h, off, csr, Wl2, bl2, out, N_NODES, 1); // 8
}

// round 5
// speedup vs baseline: 1.2885x; 1.0422x over previous
#include <cuda_runtime.h>
#include <math.h>

#define N_NODES 25000
#define N_EDGES 400000
#define HID 64
#define HEADS 4
#define D1 (HID*HEADS)

typedef unsigned long long u64;

// ---------------- scratch (static device globals; no allocation) -------------
__device__ float g_h[N_NODES * HID];
__device__ float g_x[N_NODES * D1];
__device__ int   g_deg[N_NODES];
__device__ int   g_off[N_NODES + 1];
__device__ int   g_cur[N_NODES];
__device__ int   g_csr[N_EDGES];

// ---------------- helpers -----------------------------------------------------
__device__ __forceinline__ float ex2_approx(float x) {
    float r;
    asm("ex2.approx.ftz.f32 %0, %1;" : "=f"(r) : "f"(x));
    return r;
}
__device__ __forceinline__ u64 pk2(float lo, float hi) {
    u64 r; asm("mov.b64 %0, {%1, %2};" : "=l"(r) : "f"(lo), "f"(hi)); return r;
}
__device__ __forceinline__ void upk2(float& lo, float& hi, u64 v) {
    asm("mov.b64 {%0, %1}, %2;" : "=f"(lo), "=f"(hi) : "l"(v));
}
__device__ __forceinline__ u64 fma2(u64 a, u64 b, u64 c) {
    u64 r; asm("fma.rn.f32x2 %0, %1, %2, %3;" : "=l"(r) : "l"(a), "l"(b), "l"(c)); return r;
}
__device__ __forceinline__ u64 mul2(u64 a, u64 b) {
    u64 r; asm("mul.rn.f32x2 %0, %1, %2;" : "=l"(r) : "l"(a), "l"(b)); return r;
}
__device__ __forceinline__ u64 add2(u64 a, u64 b) {
    u64 r; asm("add.rn.f32x2 %0, %1, %2;" : "=l"(r) : "l"(a), "l"(b)); return r;
}

// ---------------- CSR build --------------------------------------------------
__global__ void k_count(const int* __restrict__ recv, int* __restrict__ deg, int E) {
    int i = blockIdx.x * blockDim.x + threadIdx.x;
    if (i < E) atomicAdd(&deg[recv[i]], 1);
}

__global__ __launch_bounds__(1024)
void k_scan(const int* __restrict__ deg, int* __restrict__ off,
            int* __restrict__ cur, int n) {
    __shared__ int wsum[32];
    __shared__ int carry_s;
    int t    = threadIdx.x;
    int lane = t & 31;
    int wid  = t >> 5;
    if (t == 0) { carry_s = 0; off[0] = 0; }
    __syncthreads();
    for (int base = 0; base < n; base += 1024) {
        int i = base + t;
        int v = (i < n) ? deg[i] : 0;
        int s = v;
#pragma unroll
        for (int o = 1; o < 32; o <<= 1) {
            int u = __shfl_up_sync(0xffffffffu, s, o);
            if (lane >= o) s += u;
        }
        if (lane == 31) wsum[wid] = s;
        __syncthreads();
        if (wid == 0) {
            int ws = wsum[lane];
#pragma unroll
            for (int o = 1; o < 32; o <<= 1) {
                int u = __shfl_up_sync(0xffffffffu, ws, o);
                if (lane >= o) ws += u;
            }
            wsum[lane] = ws;
        }
        __syncthreads();
        int prev  = (wid > 0) ? wsum[wid - 1] : 0;
        int carry = carry_s;
        int incl  = carry + prev + s;
        if (i < n) {
            off[i + 1] = incl;
            cur[i]     = incl - v;
        }
        __syncthreads();
        if (t == 1023) carry_s = incl;
        __syncthreads();
    }
}

// scatter also re-zeroes deg (dead after k_scan) so the next replay starts clean.
__global__ void k_scatter(const int* __restrict__ recv, const int* __restrict__ send,
                          int* __restrict__ cur, int* __restrict__ csr,
                          int* __restrict__ deg, int E) {
    int i = blockIdx.x * blockDim.x + threadIdx.x;
    if (i < N_NODES) deg[i] = 0;
    if (i < E) {
        int r = recv[i];
        int p = atomicAdd(&cur[r], 1);
        csr[p] = send[i];
    }
}

// ---------------- SIMT GEMM v2: h[M,64] = x[M,K] @ Wq[K,64] + bq --------------
// 64x64 tile, 256 threads, 4x4 microtile, A staged TRANSPOSED so the inner
// loop is 2x LDS.128 broadcast + 16 FFMA. Low regs -> high occupancy; small
// tiles -> 391 blocks -> per-SM imbalance ~14% instead of 2x.
#define GT_KC 32
#define AP 68   // padded A row: 4-way stage conflict, aligned float4 reads

__global__ __launch_bounds__(256, 5)
void k_gemm(const float* __restrict__ x, const float* __restrict__ Wq,
            const float* __restrict__ bq, float* __restrict__ h,
            int M, int K) {
    __shared__ float As[GT_KC * AP];   // transposed: As[k*AP + m]
    __shared__ float Bs[GT_KC * 64];
    int t  = threadIdx.x;
    int tx = t & 15;    // cols 4*tx..+3
    int ty = t >> 4;    // rows 4*ty..+3
    int m0 = blockIdx.x * 64;

    float acc[4][4];
#pragma unroll
    for (int r = 0; r < 4; r++)
#pragma unroll
        for (int c = 0; c < 4; c++) acc[r][c] = 0.f;

    for (int k0 = 0; k0 < K; k0 += GT_KC) {
        // stage A (64 rows x 32 k), transposed into As[k][m]
#pragma unroll
        for (int i = 0; i < 2; i++) {
            int f  = t + i * 256;        // 0..511 float4 slots
            int r  = f >> 3;             // row 0..63
            int c4 = (f & 7) * 4;        // k offset 0..28
            int gr = m0 + r;
            float4 v = (gr < M) ? *(const float4*)&x[gr * K + k0 + c4]
                                : make_float4(0.f, 0.f, 0.f, 0.f);
            As[(c4 + 0) * AP + r] = v.x;
            As[(c4 + 1) * AP + r] = v.y;
            As[(c4 + 2) * AP + r] = v.z;
            As[(c4 + 3) * AP + r] = v.w;
        }
        // stage B (32 k x 64 cols)
#pragma unroll
        for (int i = 0; i < 2; i++) {
            int f  = t + i * 256;
            int kk = f >> 4;
            int c4 = (f & 15) * 4;
            *(float4*)&Bs[kk * 64 + c4] = *(const float4*)&Wq[(k0 + kk) * 64 + c4];
        }
        __syncthreads();
#pragma unroll
        for (int kk = 0; kk < GT_KC; kk++) {
            float4 av = *(const float4*)&As[kk * AP + ty * 4];
            float4 bv = *(const float4*)&Bs[kk * 64 + tx * 4];
            float a[4] = {av.x, av.y, av.z, av.w};
            float b[4] = {bv.x, bv.y, bv.z, bv.w};
#pragma unroll
            for (int r = 0; r < 4; r++)
#pragma unroll
                for (int c = 0; c < 4; c++)
                    acc[r][c] = fmaf(a[r], b[c], acc[r][c]);
        }
        __syncthreads();
    }

    float4 bias = *(const float4*)&bq[tx * 4];
#pragma unroll
    for (int r = 0; r < 4; r++) {
        int gr = m0 + ty * 4 + r;
        if (gr < M) {
            float4 o;
            o.x = acc[r][0] + bias.x;
            o.y = acc[r][1] + bias.y;
            o.z = acc[r][2] + bias.z;
            o.w = acc[r][3] + bias.w;
            *(float4*)&h[gr * HID + tx * 4] = o;
        }
    }
}

// ---------------- fused edge attention + aggregate (f32x2 packed) ------------
__global__ __launch_bounds__(256)
void k_edge(const float* __restrict__ h, const int* __restrict__ off,
            const int* __restrict__ csr, const float* __restrict__ Wl,
            const float* __restrict__ bl, float* __restrict__ out,
            int n, int last) {
    int w = (blockIdx.x * blockDim.x + threadIdx.x) >> 5;
    if (w >= n) return;
    int lane = threadIdx.x & 31;
    const u64* hv = (const u64*)h;

    float rvx, rvy;
    upk2(rvx, rvy, hv[w * 32 + lane]);

    const float L2E = 1.4426950408889634f;
    const u64 P02 = pk2(0.2f, 0.2f);
    u64 W0p[4], cp[4];
#pragma unroll
    for (int a = 0; a < 4; a++) {
        float w0 = Wl[a] * L2E;
        float w1 = Wl[4 + a];
        float b  = bl[a];
        W0p[a] = pk2(w0, w0);
        cp[a]  = pk2(fmaf(w1, rvx, b) * L2E, fmaf(w1, rvy, b) * L2E);
    }

    int beg = off[w], end = off[w + 1];
    bool has = end > beg;

    u64 den[4], num[4];
#pragma unroll
    for (int a = 0; a < 4; a++) { den[a] = pk2(0.f, 0.f); num[a] = pk2(0.f, 0.f); }

    int i = beg;
    for (; i + 2 <= end; i += 2) {
        int sa = __ldg(&csr[i]);
        int sb = __ldg(&csr[i + 1]);
        u64 pva = hv[sa * 32 + lane];
        u64 pvb = hv[sb * 32 + lane];
#pragma unroll
        for (int a = 0; a < 4; a++) {
            u64 z2 = fma2(W0p[a], pva, cp[a]);
            u64 zs = mul2(z2, P02);
            float zl, zh, sl, sh;
            upk2(zl, zh, z2); upk2(sl, sh, zs);
            float p0 = ex2_approx(fmaxf(zl, sl));
            float p1 = ex2_approx(fmaxf(zh, sh));
            u64 pp = pk2(p0, p1);
            den[a] = add2(den[a], pp);
            num[a] = fma2(pva, pp, num[a]);
        }
#pragma unroll
        for (int a = 0; a < 4; a++) {
            u64 z2 = fma2(W0p[a], pvb, cp[a]);
            u64 zs = mul2(z2, P02);
            float zl, zh, sl, sh;
            upk2(zl, zh, z2); upk2(sl, sh, zs);
            float p0 = ex2_approx(fmaxf(zl, sl));
            float p1 = ex2_approx(fmaxf(zh, sh));
            u64 pp = pk2(p0, p1);
            den[a] = add2(den[a], pp);
            num[a] = fma2(pvb, pp, num[a]);
        }
    }
    if (i < end) {
        int sa = __ldg(&csr[i]);
        u64 pva = hv[sa * 32 + lane];
#pragma unroll
        for (int a = 0; a < 4; a++) {
            u64 z2 = fma2(W0p[a], pva, cp[a]);
            u64 zs = mul2(z2, P02);
            float zl, zh, sl, sh;
            upk2(zl, zh, z2); upk2(sl, sh, zs);
            float p0 = ex2_approx(fmaxf(zl, sl));
            float p1 = ex2_approx(fmaxf(zh, sh));
            u64 pp = pk2(p0, p1);
            den[a] = add2(den[a], pp);
            num[a] = fma2(pva, pp, num[a]);
        }
    }

    if (last) {
        float acc0 = 0.f, acc1 = 0.f;
#pragma unroll
        for (int a = 0; a < 4; a++) {
            float n0, n1, d0, d1;
            upk2(n0, n1, num[a]); upk2(d0, d1, den[a]);
            acc0 += has ? __fdividef(n0, d0) : 0.f;
            acc1 += has ? __fdividef(n1, d1) : 0.f;
        }
        float v0 = 0.25f * acc0;
        float v1 = 0.25f * acc1;
        v0 = (v0 > 0.f) ? v0 : expm1f(v0);
        v1 = (v1 > 0.f) ? v1 : expm1f(v1);
        *(float2*)&out[w * HID + 2 * lane] = make_float2(v0, v1);
    } else {
        float o[8];
#pragma unroll
        for (int a = 0; a < 4; a++) {
            float n0, n1, d0, d1;
            upk2(n0, n1, num[a]); upk2(d0, d1, den[a]);
            float g0 = has ? __fdividef(n0, d0) : 0.f;
            float g1 = has ? __fdividef(n1, d1) : 0.f;
            o[a]     = (g0 > 0.f) ? g0 : expm1f(g0);
            o[4 + a] = (g1 > 0.f) ? g1 : expm1f(g1);
        }
        *(float4*)&out[w * D1 + 8 * lane]     = make_float4(o[0], o[1], o[2], o[3]);
        *(float4*)&out[w * D1 + 8 * lane + 4] = make_float4(o[4], o[5], o[6], o[7]);
    }
}

// ---------------- launch ------------------------------------------------------
extern "C" void kernel_launch(void* const* d_in, const int* in_sizes, int n_in,
                              void* d_out, int out_size) {
    const float* nodes = (const float*)d_in[0];
    const int*   send  = (const int*)d_in[1];
    const int*   recv  = (const int*)d_in[2];
    const float* Wq0 = (const float*)d_in[3];
    const float* bq0 = (const float*)d_in[4];
    const float* Wl0 = (const float*)d_in[5];
    const float* bl0 = (const float*)d_in[6];
    const float* Wq1 = (const float*)d_in[7];
    const float* bq1 = (const float*)d_in[8];
    const float* Wl1 = (const float*)d_in[9];
    const float* bl1 = (const float*)d_in[10];
    const float* Wq2 = (const float*)d_in[11];
    const float* bq2 = (const float*)d_in[12];
    const float* Wl2 = (const float*)d_in[13];
    const float* bl2 = (const float*)d_in[14];
    float* out = (float*)d_out;

    float *h, *x;
    int *deg, *off, *cur, *csr;
    cudaGetSymbolAddress((void**)&h,   g_h);
    cudaGetSymbolAddress((void**)&x,   g_x);
    cudaGetSymbolAddress((void**)&deg, g_deg);
    cudaGetSymbolAddress((void**)&off, g_off);
    cudaGetSymbolAddress((void**)&cur, g_cur);
    cudaGetSymbolAddress((void**)&csr, g_csr);

    int gemm_blocks = (N_NODES + 63) / 64;
    int edge_blocks = (N_NODES * 32 + 255) / 256;

    // launch index 3 (k_gemm layer0) is the one ncu profiles — keep it there.
    k_count<<<(N_EDGES + 255) / 256, 256>>>(recv, deg, N_EDGES);          // 0
    k_scan<<<1, 1024>>>(deg, off, cur, N_NODES);                          // 1
    k_scatter<<<(N_EDGES + 255) / 256, 256>>>(recv, send, cur, csr, deg, N_EDGES); // 2
    k_gemm<<<gemm_blocks, 256>>>(nodes, Wq0, bq0, h, N_NODES, 128);       // 3 (profiled)
    k_edge<<<edge_blocks, 256>>>(h, off, csr, Wl0, bl0, x, N_NODES, 0);   // 4
    k_gemm<<<gemm_blocks, 256>>>(x, Wq1, bq1, h, N_NODES, D1);            // 5
    k_edge<<<edge_blocks, 256>>>(h, off, csr, Wl1, bl1, x, N_NODES, 0);   // 6
    k_gemm<<<gemm_blocks, 256>>>(x, Wq2, bq2, h, N_NODES, D1);            // 7
    k_edge<<<edge_blocks, 256>>>(h, off, csr, Wl2, bl2, out, N_NODES, 1); // 8
}